// round 9
// baseline (speedup 1.0000x reference)
#include <cuda_runtime.h>

// DPLSafePolicy fused skinny GEMM (16384x2048 @ 2048x13) + softmax/ProbLog epilogue.
// R6: kill the weight-LDS duplication. Lane = (col-group g x output-group o); each
// lane accumulates ALL 4 rows for its 4 outputs (o=3 clamps to plane 12). LDS.128
// count per chunk drops 832 -> 256 (the R5 L1 bottleneck at 66%). K-packed
// fma.rn.f32x2, 4-col stages, x loaded as double2 (4 rows, 4-way o-dup via L1
// broadcast). 3-level g-shfl reduce + smem bounce, epilogue on lanes 0..3.

#define GRIDX 296              // 2 CTAs per SM
#define NTHR 448               // 14 warps/CTA -> 4144 warps >= 4096 chunks, 73-reg cap
#define HDIM 2048
#define NROWS 16384
#define RPC 4
#define NCHUNK (NROWS / RPC)   // 4096
#define PS 2076                // plane stride in floats
#define SCRATCH_PW 56          // scratch floats per warp (4 rows x 14)
#define SMEM_FLOATS (13 * PS + (NTHR / 32) * SCRATCH_PW)
#define SMEM_BYTES (SMEM_FLOATS * 4)

typedef unsigned long long u64;

__device__ __forceinline__ u64 fma2(u64 a, u64 b, u64 c) {
    u64 d; asm("fma.rn.f32x2 %0, %1, %2, %3;" : "=l"(d) : "l"(a), "l"(b), "l"(c)); return d;
}
__device__ __forceinline__ void unpack2(u64 a, float& lo, float& hi) {
    asm("mov.b64 {%0, %1}, %2;" : "=f"(lo), "=f"(hi) : "l"(a));
}
__device__ __forceinline__ void pf_l2(const float* p) {
    asm volatile("prefetch.global.L2 [%0];" :: "l"(p));
}
__device__ __forceinline__ int swz(int c) { return c + ((c >> 8) << 2); }

__global__ void __launch_bounds__(NTHR, 2) policy_kernel(
    const float* __restrict__ x,
    const float* __restrict__ Wg, const float* __restrict__ bg,
    const float* __restrict__ Wp, const float* __restrict__ bp,
    const float* __restrict__ Wa, const float* __restrict__ ba,
    float* __restrict__ out)
{
    extern __shared__ float sw[];
    float* sred = sw + 13 * PS;
    const int tid = threadIdx.x;

    // Pack weights into 13 planes: sw[j*PS + swz(c)] = W[c, j]
    for (int t = tid; t < HDIM * 4; t += NTHR) {
        int c = t >> 2, j = t & 3;
        float vg = Wg[t], vp = Wp[t];
        sw[j * PS + swz(c)] = vg;
        sw[(j + 4) * PS + swz(c)] = vp;
    }
    for (int t = tid; t < HDIM * 5; t += NTHR) {
        int c = t / 5, j = t - c * 5;
        sw[(j + 8) * PS + swz(c)] = Wa[t];
    }
    __syncthreads();

    const int warp = tid >> 5, lane = tid & 31;
    const int chunk = warp * GRIDX + blockIdx.x;   // interleaved over SMs
    if (chunk >= NCHUNK) return;

    const int o = lane & 3;           // output group (0..3): planes 4o..4o+3 (clamped 12)
    const int g = lane >> 2;          // column group (0..7), 256 cols each
    const int r0 = chunk * RPC;
    const float* xb = x + (size_t)r0 * HDIM + (g << 8);   // row 0 of chunk, group base

    // 4 weight-plane pointers for this lane (o=3 -> all clamp to plane 12)
    const float* wp0; const float* wp1; const float* wp2; const float* wp3;
    {
        int j0 = 4 * o;
        wp0 = sw + min(j0 + 0, 12) * PS + g * 260;
        wp1 = sw + min(j0 + 1, 12) * PS + g * 260;
        wp2 = sw + min(j0 + 2, 12) * PS + g * 260;
        wp3 = sw + min(j0 + 3, 12) * PS + g * 260;
    }

    u64 acc[4][4];   // [row][k], K-packed (even,odd) partial sums
#pragma unroll
    for (int r = 0; r < 4; r++)
#pragma unroll
        for (int k = 0; k < 4; k++) acc[r][k] = 0;

#pragma unroll 1
    for (int cl = 0; cl < 256; cl += 4) {
        if ((cl & 31) == 0) {          // L2 prefetch ~96 cols ahead, all 4 rows
            int pfc = cl + 96; if (pfc > 252) pfc = 252;
            pf_l2(xb + pfc);
            pf_l2(xb + HDIM + pfc);
            pf_l2(xb + 2 * HDIM + pfc);
            pf_l2(xb + 3 * HDIM + pfc);
        }
        // x: 4 rows x 4 cols, K-packed pairs straight from LDG.128
        double2 xr0 = *(const double2*)(xb + cl);
        double2 xr1 = *(const double2*)(xb + HDIM + cl);
        double2 xr2 = *(const double2*)(xb + 2 * HDIM + cl);
        double2 xr3 = *(const double2*)(xb + 3 * HDIM + cl);
        u64 x0a = __double_as_longlong(xr0.x), x0b = __double_as_longlong(xr0.y);
        u64 x1a = __double_as_longlong(xr1.x), x1b = __double_as_longlong(xr1.y);
        u64 x2a = __double_as_longlong(xr2.x), x2b = __double_as_longlong(xr2.y);
        u64 x3a = __double_as_longlong(xr3.x), x3b = __double_as_longlong(xr3.y);

#define JSTEP(k, wp_) { \
            double2 wd = *(const double2*)(wp_ + cl); \
            u64 wa = __double_as_longlong(wd.x), wb_ = __double_as_longlong(wd.y); \
            acc[0][k] = fma2(x0a, wa, acc[0][k]); acc[0][k] = fma2(x0b, wb_, acc[0][k]); \
            acc[1][k] = fma2(x1a, wa, acc[1][k]); acc[1][k] = fma2(x1b, wb_, acc[1][k]); \
            acc[2][k] = fma2(x2a, wa, acc[2][k]); acc[2][k] = fma2(x2b, wb_, acc[2][k]); \
            acc[3][k] = fma2(x3a, wa, acc[3][k]); acc[3][k] = fma2(x3b, wb_, acc[3][k]); \
        }
        JSTEP(0, wp0); JSTEP(1, wp1); JSTEP(2, wp2); JSTEP(3, wp3);
#undef JSTEP
    }

    // horizontal even+odd, then reduce over g (lane bits 2,3,4)
    float v[4][4];
#pragma unroll
    for (int r = 0; r < 4; r++)
#pragma unroll
        for (int k = 0; k < 4; k++) {
            float lo, hi; unpack2(acc[r][k], lo, hi); v[r][k] = lo + hi;
        }
#pragma unroll
    for (int off = 4; off <= 16; off <<= 1)
#pragma unroll
        for (int r = 0; r < 4; r++)
#pragma unroll
            for (int k = 0; k < 4; k++)
                v[r][k] += __shfl_xor_sync(0xffffffffu, v[r][k], off);

    // g==0 lanes (0..3) publish their outputs; scratch [warp][row][j]
    float* red = sred + warp * SCRATCH_PW;
    if (g == 0) {
#pragma unroll
        for (int r = 0; r < 4; r++)
#pragma unroll
            for (int k = 0; k < 4; k++) {
                int j = 4 * o + k;
                if (j <= 12) red[r * 14 + j] = v[r][k];
            }
    }
    __syncwarp();

    if (lane < 4) {
        const int row = r0 + lane;
        const float* rv = red + lane * 14;
        float l0 = rv[0] + bg[0], l1 = rv[1] + bg[1], l2 = rv[2] + bg[2], l3 = rv[3] + bg[3];
        float mg = fmaxf(fmaxf(l0, l1), fmaxf(l2, l3));
        float eg0 = __expf(l0 - mg), eg1 = __expf(l1 - mg), eg2 = __expf(l2 - mg), eg3 = __expf(l3 - mg);
        float sg = eg0 + eg1 + eg2 + eg3;
        float p0 = rv[4] + bp[0], p1 = rv[5] + bp[1], p2 = rv[6] + bp[2], p3 = rv[7] + bp[3];
        float mp = fmaxf(fmaxf(p0, p1), fmaxf(p2, p3));
        float ep0 = __expf(p0 - mp), ep1 = __expf(p1 - mp), ep2 = __expf(p2 - mp), ep3 = __expf(p3 - mp);
        float sp = ep0 + ep1 + ep2 + ep3;
        float q0 = rv[8] + ba[0], q1 = rv[9] + ba[1], q2 = rv[10] + ba[2], q3 = rv[11] + ba[3], q4 = rv[12] + ba[4];
        float ma = fmaxf(fmaxf(fmaxf(q0, q1), fmaxf(q2, q3)), q4);
        float ea0 = __expf(q0 - ma), ea1 = __expf(q1 - ma), ea2 = __expf(q2 - ma),
              ea3 = __expf(q3 - ma), ea4 = __expf(q4 - ma);
        float t0 = ep0 * eg0 + ep1 * eg1 + ep2 * eg2 + ep3 * eg3;  // stay
        float t1 = ep0 * eg1 + ep2 * eg3;                           // up
        float t2 = ep1 * eg0 + ep3 * eg2;                           // down
        float inv = 1.0f / (sg * sp);
        float j0 = ea0 * (1.0f - t0 * inv);
        float j1 = ea1 * (1.0f - t1 * inv);
        float j2 = ea2 * (1.0f - t2 * inv);
        float s = j0 + j1 + j2 + ea3 + ea4;
        float is = 1.0f / s;
        float* oo = out + (size_t)row * 5;
        oo[0] = j0 * is; oo[1] = j1 * is; oo[2] = j2 * is; oo[3] = ea3 * is; oo[4] = ea4 * is;
    }
}

extern "C" void kernel_launch(void* const* d_in, const int* in_sizes, int n_in,
                              void* d_out, int out_size)
{
    const float* x  = (const float*)d_in[0];
    const float* Wg = (const float*)d_in[1];
    const float* bg = (const float*)d_in[2];
    const float* Wp = (const float*)d_in[3];
    const float* bp = (const float*)d_in[4];
    const float* Wa = (const float*)d_in[5];
    const float* ba = (const float*)d_in[6];
    float* out = (float*)d_out;

    cudaFuncSetAttribute(policy_kernel, cudaFuncAttributeMaxDynamicSharedMemorySize, SMEM_BYTES);
    policy_kernel<<<GRIDX, NTHR, SMEM_BYTES>>>(x, Wg, bg, Wp, bp, Wa, ba, out);
}

// round 10
// speedup vs baseline: 1.5120x; 1.5120x over previous
#include <cuda_runtime.h>

// DPLSafePolicy fused skinny GEMM (16384x2048 @ 2048x13) + softmax/ProbLog epilogue.
// R7: fix x-LDG scatter. g-slices are now 8-col interleaved slices inside 64-col
// stages (not 256-col blocks), so each x LDG.128 touches 8 full-consumed lines
// (512B/4rows contiguous per row) instead of 32 lines x 16B: 4x fewer L1
// wavefronts. Weights plane-contiguous with 16B pad per 64 cols (conflict-free
// broadcast LDS.128, 110.5KB, 2 CTAs/SM). Packed-K fma.rn.f32x2 as R5.

#define GRIDX 296              // 2 CTAs per SM
#define NTHR 512
#define HDIM 2048
#define NROWS 16384
#define RPC 4
#define NCHUNK (NROWS / RPC)   // 4096
#define PSF 2176               // plane stride floats: 2048 + 32 blocks... (2048 + (2048/64)*4)
#define SMEM_FLOATS (13 * PSF)
#define SMEM_BYTES (SMEM_FLOATS * 4)

typedef unsigned long long u64;

__device__ __forceinline__ u64 fma2(u64 a, u64 b, u64 c) {
    u64 d; asm("fma.rn.f32x2 %0, %1, %2, %3;" : "=l"(d) : "l"(a), "l"(b), "l"(c)); return d;
}
__device__ __forceinline__ void unpack2(u64 a, float& lo, float& hi) {
    asm("mov.b64 {%0, %1}, %2;" : "=f"(lo), "=f"(hi) : "l"(a));
}
__device__ __forceinline__ void pf_l2(const float* p) {
    asm volatile("prefetch.global.L2 [%0];" :: "l"(p));
}
// plane-local offset: 16B pad after every 64 cols
__device__ __forceinline__ int woff(int c) { return c + ((c >> 6) << 2); }

__global__ void __launch_bounds__(NTHR, 2) policy_kernel(
    const float* __restrict__ x,
    const float* __restrict__ Wg, const float* __restrict__ bg,
    const float* __restrict__ Wp, const float* __restrict__ bp,
    const float* __restrict__ Wa, const float* __restrict__ ba,
    float* __restrict__ out)
{
    extern __shared__ float sw[];
    const int tid = threadIdx.x;

    // Pack weights into 13 contiguous planes with 16B pad per 64 cols:
    // sw[j*PSF + woff(c)] = W[c, j]
    for (int t = tid; t < HDIM * 4; t += NTHR) {
        int c = t >> 2, j = t & 3;
        float vg = Wg[t], vp = Wp[t];
        int o = woff(c);
        sw[j * PSF + o] = vg;
        sw[(j + 4) * PSF + o] = vp;
    }
    for (int t = tid; t < HDIM * 5; t += NTHR) {
        int c = t / 5, j = t - c * 5;
        sw[(j + 8) * PSF + woff(c)] = Wa[t];
    }
    __syncthreads();

    const int warp = tid >> 5, lane = tid & 31;
    const int chunk = warp * GRIDX + blockIdx.x;   // interleaved over SMs
    if (chunk >= NCHUNK) return;

    const int rsub = lane & 3;        // row within chunk (0..3)
    const int g = lane >> 2;          // 8-col slice within each 64-col stage
    const int r0 = chunk * RPC;
    // lane's x base: row, slice offset. Stage ss adds ss*64.
    const float* xb = x + (size_t)(r0 + rsub) * HDIM + (g << 3);
    // lane's weight base within a plane: g*8 floats (stage ss adds ss*68 floats: 64 cols + 4 pad)
    const float* wb = sw + (g << 3);

    u64 acc[13];
#pragma unroll
    for (int j = 0; j < 13; j++) acc[j] = 0;

    // stage 0 x (8 cols = 4 K-pairs)
    double2 xa = *(const double2*)(xb);
    double2 xc = *(const double2*)(xb + 4);
    u64 x01 = __double_as_longlong(xa.x), x23 = __double_as_longlong(xa.y);
    u64 x45 = __double_as_longlong(xc.x), x67 = __double_as_longlong(xc.y);

#pragma unroll 1
    for (int ss = 0; ss < 32; ss++) {
        const int xoff = ss << 6;              // global col base of this stage
        // next-stage x (1-stage register double buffer)
        u64 n01 = 0, n23 = 0, n45 = 0, n67 = 0;
        if (ss < 31) {
            double2 na = *(const double2*)(xb + xoff + 64);
            double2 nc = *(const double2*)(xb + xoff + 68);
            n01 = __double_as_longlong(na.x); n23 = __double_as_longlong(na.y);
            n45 = __double_as_longlong(nc.x); n67 = __double_as_longlong(nc.y);
        }
        if ((ss & 1) == 0) {                   // L2 prefetch ~2 stages ahead
            int pfc = xoff + 128; if (pfc > 1984) pfc = 1984;
            pf_l2(xb + pfc);
        }
        const float* wstage = wb + ss * 68;    // 64 cols + 4 pad floats per stage
#pragma unroll
        for (int j = 0; j < 13; j++) {
            const float* wp_ = wstage + j * PSF;
            double2 w0 = *(const double2*)(wp_);        // K-pairs (c0,c1),(c2,c3)
            double2 w1 = *(const double2*)(wp_ + 4);    // (c4,c5),(c6,c7)
            u64 a = acc[j];
            a = fma2(x01, __double_as_longlong(w0.x), a);
            a = fma2(x23, __double_as_longlong(w0.y), a);
            a = fma2(x45, __double_as_longlong(w1.x), a);
            a = fma2(x67, __double_as_longlong(w1.y), a);
            acc[j] = a;
        }
        x01 = n01; x23 = n23; x45 = n45; x67 = n67;
    }

    float v[13];
#pragma unroll
    for (int j = 0; j < 13; j++) {
        float lo, hi; unpack2(acc[j], lo, hi); v[j] = lo + hi;
    }

    // Reduce across the 8 g-slices (lane bits 2,3,4)
#pragma unroll
    for (int off = 4; off <= 16; off <<= 1) {
#pragma unroll
        for (int j = 0; j < 13; j++)
            v[j] += __shfl_xor_sync(0xffffffffu, v[j], off);
    }

    if (g == 0) {
        const int row = r0 + rsub;
        float l0 = v[0] + bg[0], l1 = v[1] + bg[1], l2 = v[2] + bg[2], l3 = v[3] + bg[3];
        float mg = fmaxf(fmaxf(l0, l1), fmaxf(l2, l3));
        float eg0 = __expf(l0 - mg), eg1 = __expf(l1 - mg), eg2 = __expf(l2 - mg), eg3 = __expf(l3 - mg);
        float sg = eg0 + eg1 + eg2 + eg3;
        float p0 = v[4] + bp[0], p1 = v[5] + bp[1], p2 = v[6] + bp[2], p3 = v[7] + bp[3];
        float mp = fmaxf(fmaxf(p0, p1), fmaxf(p2, p3));
        float ep0 = __expf(p0 - mp), ep1 = __expf(p1 - mp), ep2 = __expf(p2 - mp), ep3 = __expf(p3 - mp);
        float sp = ep0 + ep1 + ep2 + ep3;
        float q0 = v[8] + ba[0], q1 = v[9] + ba[1], q2 = v[10] + ba[2], q3 = v[11] + ba[3], q4 = v[12] + ba[4];
        float ma = fmaxf(fmaxf(fmaxf(q0, q1), fmaxf(q2, q3)), q4);
        float ea0 = __expf(q0 - ma), ea1 = __expf(q1 - ma), ea2 = __expf(q2 - ma),
              ea3 = __expf(q3 - ma), ea4 = __expf(q4 - ma);
        float t0 = ep0 * eg0 + ep1 * eg1 + ep2 * eg2 + ep3 * eg3;  // stay
        float t1 = ep0 * eg1 + ep2 * eg3;                           // up
        float t2 = ep1 * eg0 + ep3 * eg2;                           // down
        float inv = 1.0f / (sg * sp);
        float j0 = ea0 * (1.0f - t0 * inv);
        float j1 = ea1 * (1.0f - t1 * inv);
        float j2 = ea2 * (1.0f - t2 * inv);
        float s = j0 + j1 + j2 + ea3 + ea4;
        float is = 1.0f / s;
        float* o = out + (size_t)row * 5;
        o[0] = j0 * is; o[1] = j1 * is; o[2] = j2 * is; o[3] = ea3 * is; o[4] = ea4 * is;
    }
}

extern "C" void kernel_launch(void* const* d_in, const int* in_sizes, int n_in,
                              void* d_out, int out_size)
{
    const float* x  = (const float*)d_in[0];
    const float* Wg = (const float*)d_in[1];
    const float* bg = (const float*)d_in[2];
    const float* Wp = (const float*)d_in[3];
    const float* bp = (const float*)d_in[4];
    const float* Wa = (const float*)d_in[5];
    const float* ba = (const float*)d_in[6];
    float* out = (float*)d_out;

    cudaFuncSetAttribute(policy_kernel, cudaFuncAttributeMaxDynamicSharedMemorySize, SMEM_BYTES);
    policy_kernel<<<GRIDX, NTHR, SMEM_BYTES>>>(x, Wg, bg, Wp, bp, Wa, ba, out);
}